// round 4
// baseline (speedup 1.0000x reference)
#include <cuda_runtime.h>

// ---------------------------------------------------------------------------
// Scratch: ping-pong activation buffers (max layer is 1024 x 4096 fp32).
// __device__ globals: allowed (no runtime allocation).
// ---------------------------------------------------------------------------
__device__ float g_bufA[1024 * 4096];
__device__ float g_bufB[1024 * 4096];

__device__ __forceinline__ float clip1f(float x) { return fminf(fmaxf(x, -1.f), 1.f); }

// ---------------------------------------------------------------------------
// KAN activation: replicates the reference's *partial* in-place Cox-de Boor
// recursion exactly. Knots are compile-time constants; after full unrolling
// all denominators (and their reciprocals) constant-fold, so the whole thing
// is straight-line FMA/ALU code (no divisions).
// ---------------------------------------------------------------------------
__device__ __forceinline__ float kan_eval(float x, const float* __restrict__ cps, float rwv) {
    float t = tanhf(x);
    const float kn[12] = {-1.f, -1.f, -1.f, -1.f, -0.6f, -0.2f, 0.2f, 0.6f,
                          1.f, 1.f, 1.f, 1.f};
    float c[8];
#pragma unroll
    for (int i = 0; i < 8; ++i)
        c[i] = (t >= kn[i] && t < kn[i + 1]) ? 1.f : 0.f;
#pragma unroll
    for (int dg = 1; dg <= 3; ++dg) {
#pragma unroll
        for (int i = 0; i < 7; ++i) {
            if (i < 8 - dg) {
                const float d1 = kn[i + dg] - kn[i];
                const float d2 = kn[i + dg + 1] - kn[i + 1];
                float t1 = (d1 > 1e-10f) ? ((t - kn[i]) * (1.0f / d1)) * c[i] : 0.f;
                float t2 = (d2 > 1e-10f) ? ((kn[i + dg + 1] - t) * (1.0f / d2)) * c[i + 1] : 0.f;
                c[i] = t1 + t2;
            }
        }
    }
    float s = 0.f;
#pragma unroll
    for (int j = 0; j < 8; ++j) s = fmaf(c[j], cps[j], s);
    s *= rwv;
    return fminf(fmaxf(s, -10.f), 10.f);
}

// ---------------------------------------------------------------------------
// LayerNorm (no affine), one row per block, 256 threads, D = 2048.
// ---------------------------------------------------------------------------
__global__ void ln_kernel(const float* __restrict__ x, float* __restrict__ y) {
    const int D = 2048;
    const int row = blockIdx.x;
    const float* xr = x + (size_t)row * D;
    float* yr = y + (size_t)row * D;

    float s = 0.f, q = 0.f;
#pragma unroll
    for (int it = 0; it < 2; ++it) {
        int i = threadIdx.x * 4 + it * 1024;
        float4 v = *(const float4*)(xr + i);
        s += (v.x + v.y) + (v.z + v.w);
        q += v.x * v.x + v.y * v.y + v.z * v.z + v.w * v.w;
    }
#pragma unroll
    for (int o = 16; o > 0; o >>= 1) {
        s += __shfl_xor_sync(0xffffffffu, s, o);
        q += __shfl_xor_sync(0xffffffffu, q, o);
    }
    __shared__ float ss[8], qq[8];
    __shared__ float mu_s, inv_s;
    const int lane = threadIdx.x & 31, w = threadIdx.x >> 5;
    if (lane == 0) { ss[w] = s; qq[w] = q; }
    __syncthreads();
    if (threadIdx.x == 0) {
        float ts = 0.f, tq = 0.f;
#pragma unroll
        for (int i = 0; i < 8; ++i) { ts += ss[i]; tq += qq[i]; }
        float mu = ts * (1.f / D);
        float var = tq * (1.f / D) - mu * mu;
        mu_s = mu;
        inv_s = rsqrtf(var + 1e-5f);
    }
    __syncthreads();
    const float mu = mu_s, inv = inv_s;
#pragma unroll
    for (int it = 0; it < 2; ++it) {
        int i = threadIdx.x * 4 + it * 1024;
        float4 v = *(const float4*)(xr + i);
        float4 o;
        o.x = (v.x - mu) * inv;
        o.y = (v.y - mu) * inv;
        o.z = (v.z - mu) * inv;
        o.w = (v.w - mu) * inv;
        *(float4*)(yr + i) = o;
    }
}

// ---------------------------------------------------------------------------
// Fused GEMM: C[m,n] = sum_k A[m,k] * W[n,k] + bias[n]  (both K-major, "NT")
// then (KAN=1) spline activation + noncommutative pair transform.
// 128x128 block tile, BK=16, 256 threads, 8x8 per thread, register-staged
// global prefetch over a single smem buffer.
//
// Noncommutative transform: pair p = (col/2), generator g = p % 4. Columns
// owned by a thread are an 8-aligned group, so its 4 pairs see g = 0,1,2,3.
// g=2 (sigma_z) and g=3 (I) have comm == 0 -> identity. Only applied:
//   g=0: a' = a + 0.05*clip(b),  b' = b + 0.05*clip(a)
//   g=1: a' = a + 0.05*clip(-b), b' = b + 0.05*clip(a)
// ---------------------------------------------------------------------------
template <int KAN>
__global__ void __launch_bounds__(256, 2)
gemm_fused(const float* __restrict__ A, const float* __restrict__ W,
           const float* __restrict__ bias, const float* __restrict__ cp,
           const float* __restrict__ rw, float* __restrict__ C,
           int M, int N, int K) {
    constexpr int BM = 128, BN = 128, BK = 16;
    __shared__ __align__(16) float As[BK][BM];
    __shared__ __align__(16) float Bs[BK][BN];

    const int tid = threadIdx.x;
    const int tx = tid & 15;   // column group 0..15
    const int ty = tid >> 4;   // row group 0..15
    const int row0 = blockIdx.y * BM;
    const int col0 = blockIdx.x * BN;

    // Loader mapping: each thread loads one float4 (4 consecutive k) for two
    // rows (lrow, lrow+64) of both A and W tiles.
    const int lrow = tid >> 2;          // 0..63
    const int lk = (tid & 3) << 2;      // 0,4,8,12

    const float* Aptr = A + (size_t)(row0 + lrow) * K + lk;
    const float* Wptr = W + (size_t)(col0 + lrow) * K + lk;

    float acc[8][8];
#pragma unroll
    for (int i = 0; i < 8; ++i)
#pragma unroll
        for (int j = 0; j < 8; ++j) acc[i][j] = 0.f;

    // Preload first k-tile into registers.
    float4 pa0 = *(const float4*)(Aptr);
    float4 pa1 = *(const float4*)(Aptr + (size_t)64 * K);
    float4 pb0 = *(const float4*)(Wptr);
    float4 pb1 = *(const float4*)(Wptr + (size_t)64 * K);

    for (int kt = 0; kt < K; kt += BK) {
        As[lk + 0][lrow] = pa0.x; As[lk + 1][lrow] = pa0.y;
        As[lk + 2][lrow] = pa0.z; As[lk + 3][lrow] = pa0.w;
        As[lk + 0][lrow + 64] = pa1.x; As[lk + 1][lrow + 64] = pa1.y;
        As[lk + 2][lrow + 64] = pa1.z; As[lk + 3][lrow + 64] = pa1.w;
        Bs[lk + 0][lrow] = pb0.x; Bs[lk + 1][lrow] = pb0.y;
        Bs[lk + 2][lrow] = pb0.z; Bs[lk + 3][lrow] = pb0.w;
        Bs[lk + 0][lrow + 64] = pb1.x; Bs[lk + 1][lrow + 64] = pb1.y;
        Bs[lk + 2][lrow + 64] = pb1.z; Bs[lk + 3][lrow + 64] = pb1.w;
        __syncthreads();

        if (kt + BK < K) {  // prefetch next tile while computing this one
            pa0 = *(const float4*)(Aptr + kt + BK);
            pa1 = *(const float4*)(Aptr + (size_t)64 * K + kt + BK);
            pb0 = *(const float4*)(Wptr + kt + BK);
            pb1 = *(const float4*)(Wptr + (size_t)64 * K + kt + BK);
        }

#pragma unroll
        for (int k = 0; k < BK; ++k) {
            float av[8], bv[8];
            *(float4*)(av) = *(const float4*)(&As[k][ty * 8]);
            *(float4*)(av + 4) = *(const float4*)(&As[k][ty * 8 + 4]);
            *(float4*)(bv) = *(const float4*)(&Bs[k][tx * 8]);
            *(float4*)(bv + 4) = *(const float4*)(&Bs[k][tx * 8 + 4]);
#pragma unroll
            for (int i = 0; i < 8; ++i)
#pragma unroll
                for (int j = 0; j < 8; ++j)
                    acc[i][j] = fmaf(av[i], bv[j], acc[i][j]);
        }
        __syncthreads();
    }

    const int cbase = col0 + tx * 8;
    const int rbase = row0 + ty * 8;

    if (KAN) {
        // Per-column spline params loaded once, reused across 8 rows.
#pragma unroll
        for (int j = 0; j < 8; ++j) {
            const int cI = cbase + j;
            const float bj = bias[cI];
            const float rwv = rw[cI];
            float cps[8];
#pragma unroll
            for (int n = 0; n < 8; ++n) cps[n] = cp[(size_t)cI * 9 + n];
#pragma unroll
            for (int i = 0; i < 8; ++i)
                acc[i][j] = kan_eval(acc[i][j] + bj, cps, rwv);
        }
#pragma unroll
        for (int i = 0; i < 8; ++i) {
            float* v = acc[i];
            // pair (0,1): generator sigma_x
            float a = v[0], b = v[1];
            v[0] = fmaf(0.05f, clip1f(b), a);
            v[1] = fmaf(0.05f, clip1f(a), b);
            // pair (2,3): generator sigma_y
            a = v[2]; b = v[3];
            v[2] = fmaf(0.05f, clip1f(-b), a);
            v[3] = fmaf(0.05f, clip1f(a), b);
            // pairs (4,5),(6,7): sigma_z and I -> identity
            float4* out = (float4*)(C + (size_t)(rbase + i) * N + cbase);
            out[0] = make_float4(v[0], v[1], v[2], v[3]);
            out[1] = make_float4(v[4], v[5], v[6], v[7]);
        }
    } else {
        float bl[8];
#pragma unroll
        for (int j = 0; j < 8; ++j) bl[j] = bias[cbase + j];
#pragma unroll
        for (int i = 0; i < 8; ++i) {
            float4* out = (float4*)(C + (size_t)(rbase + i) * N + cbase);
            out[0] = make_float4(acc[i][0] + bl[0], acc[i][1] + bl[1],
                                 acc[i][2] + bl[2], acc[i][3] + bl[3]);
            out[1] = make_float4(acc[i][4] + bl[4], acc[i][5] + bl[5],
                                 acc[i][6] + bl[6], acc[i][7] + bl[7]);
        }
    }
}

// ---------------------------------------------------------------------------
// Launch: LN -> (GEMM+KAN+pair) x3 -> GEMM+bias. All graph-capturable.
// Input order (metadata): x, W1,b1,cp1,rw1, W2,b2,cp2,rw2, W3,b3,cp3,rw3,
//                         W_out, b_out. Output fp32 [1024, 2048].
// ---------------------------------------------------------------------------
extern "C" void kernel_launch(void* const* d_in, const int* in_sizes, int n_in,
                              void* d_out, int out_size) {
    const float* x = (const float*)d_in[0];
    const float* W1 = (const float*)d_in[1];
    const float* b1 = (const float*)d_in[2];
    const float* cp1 = (const float*)d_in[3];
    const float* rw1 = (const float*)d_in[4];
    const float* W2 = (const float*)d_in[5];
    const float* b2 = (const float*)d_in[6];
    const float* cp2 = (const float*)d_in[7];
    const float* rw2 = (const float*)d_in[8];
    const float* W3 = (const float*)d_in[9];
    const float* b3 = (const float*)d_in[10];
    const float* cp3 = (const float*)d_in[11];
    const float* rw3 = (const float*)d_in[12];
    const float* Wo = (const float*)d_in[13];
    const float* bo = (const float*)d_in[14];

    // Resolve scratch symbol addresses once (non-stream API; capture-safe,
    // but hoisting removes it from the replay path entirely).
    static float* bufA = nullptr;
    static float* bufB = nullptr;
    if (!bufA) {
        cudaGetSymbolAddress((void**)&bufA, g_bufA);
        cudaGetSymbolAddress((void**)&bufB, g_bufB);
    }

    const int M = 1024;
    dim3 blk(256);

    ln_kernel<<<M, 256>>>(x, bufA);

    gemm_fused<1><<<dim3(4096 / 128, M / 128), blk>>>(bufA, W1, b1, cp1, rw1, bufB,
                                                      M, 4096, 2048);
    gemm_fused<1><<<dim3(4096 / 128, M / 128), blk>>>(bufB, W2, b2, cp2, rw2, bufA,
                                                      M, 4096, 4096);
    gemm_fused<1><<<dim3(2048 / 128, M / 128), blk>>>(bufA, W3, b3, cp3, rw3, bufB,
                                                      M, 2048, 4096);
    gemm_fused<0><<<dim3(2048 / 128, M / 128), blk>>>(bufB, Wo, bo, nullptr, nullptr,
                                                      (float*)d_out, M, 2048, 2048);
}

// round 6
// speedup vs baseline: 2.2431x; 2.2431x over previous
#include <cuda_runtime.h>
#include <cuda_bf16.h>
#include <cstdint>

// ===========================================================================
// Scratch (static __device__ globals — no runtime allocation).
// Activation ping-pong: pre-split bf16 hi/lo planes, 1024 x 4096 max.
// Weight planes: all four matrices pre-split once per launch.
//   W1 4096x2048 (8388608), W2 4096x4096 (16777216),
//   W3 2048x4096 (8388608), Wo 2048x2048 (4194304)  -> total 37748736
// ===========================================================================
__device__ __nv_bfloat16 g_Ahi[1024 * 4096];
__device__ __nv_bfloat16 g_Alo[1024 * 4096];
__device__ __nv_bfloat16 g_Bhi[1024 * 4096];
__device__ __nv_bfloat16 g_Blo[1024 * 4096];
__device__ __nv_bfloat16 g_Whi[37748736];
__device__ __nv_bfloat16 g_Wlo[37748736];

static const size_t W_OFF1 = 0;
static const size_t W_OFF2 = 8388608;
static const size_t W_OFF3 = 25165824;
static const size_t W_OFFO = 33554432;

// ===========================================================================
// PTX helpers (all arch-agnostic: sm_80-era instructions, valid on sm_103)
// ===========================================================================
__device__ __forceinline__ uint32_t smem_u32(const void* p) {
    uint32_t a;
    asm("{ .reg .u64 t; cvta.to.shared.u64 t, %1; cvt.u32.u64 %0, t; }" : "=r"(a) : "l"(p));
    return a;
}
#define CP_ASYNC16(sa, ga) \
    asm volatile("cp.async.cg.shared.global [%0], [%1], 16;" ::"r"(sa), "l"(ga) : "memory")
#define CP_COMMIT() asm volatile("cp.async.commit_group;" ::: "memory")
#define CP_WAIT1() asm volatile("cp.async.wait_group 1;" ::: "memory")

#define LDMX4(r0, r1, r2, r3, addr)                                       \
    asm volatile("ldmatrix.sync.aligned.m8n8.x4.shared.b16 {%0,%1,%2,%3}, [%4];" \
                 : "=r"(r0), "=r"(r1), "=r"(r2), "=r"(r3) : "r"(addr))

#define MMA16816(c, a, b0, b1)                                                     \
    asm volatile(                                                                  \
        "mma.sync.aligned.m16n8k16.row.col.f32.bf16.bf16.f32 "                     \
        "{%0,%1,%2,%3}, {%4,%5,%6,%7}, {%8,%9}, {%0,%1,%2,%3};"                    \
        : "+f"((c)[0]), "+f"((c)[1]), "+f"((c)[2]), "+f"((c)[3])                   \
        : "r"((a)[0]), "r"((a)[1]), "r"((a)[2]), "r"((a)[3]), "r"(b0), "r"(b1))

__device__ __forceinline__ uint32_t pack_bf2(float a, float b) {
    __nv_bfloat162 t = __floats2bfloat162_rn(a, b);
    return *reinterpret_cast<uint32_t*>(&t);
}
__device__ __forceinline__ float clip1f(float x) { return fminf(fmaxf(x, -1.f), 1.f); }

// ---------------------------------------------------------------------------
// KAN activation — exact replica of the reference's partial Cox-de Boor with
// constant-folded knots (validated at rel_err 8.8e-7 in R4).
// ---------------------------------------------------------------------------
__device__ __forceinline__ float kan_eval(float x, const float* __restrict__ cps, float rwv) {
    float t = tanhf(x);
    const float kn[12] = {-1.f, -1.f, -1.f, -1.f, -0.6f, -0.2f, 0.2f, 0.6f, 1.f, 1.f, 1.f, 1.f};
    float c[8];
#pragma unroll
    for (int i = 0; i < 8; ++i) c[i] = (t >= kn[i] && t < kn[i + 1]) ? 1.f : 0.f;
#pragma unroll
    for (int dg = 1; dg <= 3; ++dg) {
#pragma unroll
        for (int i = 0; i < 7; ++i) {
            if (i < 8 - dg) {
                const float d1 = kn[i + dg] - kn[i];
                const float d2 = kn[i + dg + 1] - kn[i + 1];
                float t1 = (d1 > 1e-10f) ? ((t - kn[i]) * (1.0f / d1)) * c[i] : 0.f;
                float t2 = (d2 > 1e-10f) ? ((kn[i + dg + 1] - t) * (1.0f / d2)) * c[i + 1] : 0.f;
                c[i] = t1 + t2;
            }
        }
    }
    float s = 0.f;
#pragma unroll
    for (int j = 0; j < 8; ++j) s = fmaf(c[j], cps[j], s);
    s *= rwv;
    return fminf(fmaxf(s, -10.f), 10.f);
}

// ===========================================================================
// Weight split: fp32 -> bf16 hi/lo planes (residual split).
// ===========================================================================
__global__ void wsplit(const float4* __restrict__ w, uint2* __restrict__ hi,
                       uint2* __restrict__ lo, int n4) {
    int i = blockIdx.x * blockDim.x + threadIdx.x;
    if (i >= n4) return;
    float4 v = w[i];
    __nv_bfloat16 h0 = __float2bfloat16_rn(v.x), h1 = __float2bfloat16_rn(v.y);
    __nv_bfloat16 h2 = __float2bfloat16_rn(v.z), h3 = __float2bfloat16_rn(v.w);
    uint32_t hi01 = ((uint32_t)__bfloat16_as_ushort(h1) << 16) | __bfloat16_as_ushort(h0);
    uint32_t hi23 = ((uint32_t)__bfloat16_as_ushort(h3) << 16) | __bfloat16_as_ushort(h2);
    hi[i] = make_uint2(hi01, hi23);
    lo[i] = make_uint2(pack_bf2(v.x - __bfloat162float(h0), v.y - __bfloat162float(h1)),
                       pack_bf2(v.z - __bfloat162float(h2), v.w - __bfloat162float(h3)));
}

// ===========================================================================
// LayerNorm: fp32 in -> bf16 hi/lo planes. 1 row/block, D = 2048.
// ===========================================================================
__global__ void ln_kernel(const float* __restrict__ x, __nv_bfloat16* __restrict__ yh,
                          __nv_bfloat16* __restrict__ yl) {
    const int D = 2048;
    const float* xr = x + (size_t)blockIdx.x * D;
    float s = 0.f, q = 0.f;
#pragma unroll
    for (int it = 0; it < 2; ++it) {
        float4 v = *(const float4*)(xr + threadIdx.x * 4 + it * 1024);
        s += (v.x + v.y) + (v.z + v.w);
        q += v.x * v.x + v.y * v.y + v.z * v.z + v.w * v.w;
    }
#pragma unroll
    for (int o = 16; o > 0; o >>= 1) {
        s += __shfl_xor_sync(~0u, s, o);
        q += __shfl_xor_sync(~0u, q, o);
    }
    __shared__ float ss[8], qq[8], mu_s, inv_s;
    if ((threadIdx.x & 31) == 0) { ss[threadIdx.x >> 5] = s; qq[threadIdx.x >> 5] = q; }
    __syncthreads();
    if (threadIdx.x == 0) {
        float ts = 0.f, tq = 0.f;
#pragma unroll
        for (int i = 0; i < 8; ++i) { ts += ss[i]; tq += qq[i]; }
        float mu = ts * (1.f / D);
        mu_s = mu;
        inv_s = rsqrtf(tq * (1.f / D) - mu * mu + 1e-5f);
    }
    __syncthreads();
    const float mu = mu_s, inv = inv_s;
    const size_t rb = (size_t)blockIdx.x * D;
#pragma unroll
    for (int it = 0; it < 2; ++it) {
        int i = threadIdx.x * 4 + it * 1024;
        float4 v = *(const float4*)(xr + i);
        float f0 = (v.x - mu) * inv, f1 = (v.y - mu) * inv;
        float f2 = (v.z - mu) * inv, f3 = (v.w - mu) * inv;
        __nv_bfloat16 h0 = __float2bfloat16_rn(f0), h1 = __float2bfloat16_rn(f1);
        __nv_bfloat16 h2 = __float2bfloat16_rn(f2), h3 = __float2bfloat16_rn(f3);
        uint32_t hi01 = ((uint32_t)__bfloat16_as_ushort(h1) << 16) | __bfloat16_as_ushort(h0);
        uint32_t hi23 = ((uint32_t)__bfloat16_as_ushort(h3) << 16) | __bfloat16_as_ushort(h2);
        *(uint2*)(yh + rb + i) = make_uint2(hi01, hi23);
        *(uint2*)(yl + rb + i) =
            make_uint2(pack_bf2(f0 - __bfloat162float(h0), f1 - __bfloat162float(h1)),
                       pack_bf2(f2 - __bfloat162float(h2), f3 - __bfloat162float(h3)));
    }
}

// ===========================================================================
// GEMM via mma.sync m16n8k16 bf16, x3-split, fp32 accum.
//   C[m,n] = sum_k A[m,k] W[n,k] + bias[n]; A,W given as bf16 hi/lo planes.
// BM=BN=128, BK=32, 8 warps; warp tile 64x32 (warp_m = wid&1, warp_n = wid>>1);
// 3-stage cp.async pipeline; smem rows padded to 40 elems (80 B) for
// conflict-free ldmatrix.
// KAN=1: bias + spline + pair transform -> write bf16 hi/lo planes.
// KAN=0: bias -> write fp32.
// SMEM: [0,5120) params (bias 128 | rw 128 | cp 1024 floats),
//       [5120 + st*40960): stage = {Ahi,Alo,Whi,Wlo} x (128 rows x 80 B).
// ===========================================================================
template <int KAN>
__global__ void __launch_bounds__(256, 1)
gemm_mma(const __nv_bfloat16* __restrict__ Ah, const __nv_bfloat16* __restrict__ Al,
         const __nv_bfloat16* __restrict__ Wh, const __nv_bfloat16* __restrict__ Wl,
         const float* __restrict__ bias, const float* __restrict__ cp,
         const float* __restrict__ rw, float* __restrict__ Cf,
         __nv_bfloat16* __restrict__ Chi, __nv_bfloat16* __restrict__ Clo,
         int N, int K) {
    extern __shared__ char smem[];
    float* smf = (float*)smem;
    const uint32_t sb = smem_u32(smem);
    constexpr uint32_t PARAMB = 5120, PLANE = 10240, BOFF = 20480, STAGE = 40960;

    const int tid = threadIdx.x, lane = tid & 31, wid = tid >> 5;
    const int warp_m = wid & 1, warp_n = wid >> 1;
    const int row0 = blockIdx.y * 128, col0 = blockIdx.x * 128;

    // ---- epilogue params -> smem ----
    for (int i = tid; i < 128; i += 256) {
        smf[i] = bias[col0 + i];
        if (KAN) smf[128 + i] = rw[col0 + i];
    }
    if (KAN)
        for (int i = tid; i < 1024; i += 256)
            smf[256 + i] = cp[(size_t)(col0 + (i >> 3)) * 9 + (i & 7)];

    // ---- cp.async stage loader: 2048 16B chunks, 8 per thread ----
    auto issue = [&](int kt, int st) {
#pragma unroll
        for (int i = 0; i < 8; ++i) {
            int id = tid + 256 * i;
            int half = id >> 10;          // 0 = A, 1 = W
            int rem = id & 1023;
            int plane = rem >> 9;         // 0 = hi, 1 = lo
            int r = (rem >> 2) & 127;
            int c16 = rem & 3;
            const __nv_bfloat16* gp =
                half ? ((plane ? Wl : Wh) + (size_t)(col0 + r) * K)
                     : ((plane ? Al : Ah) + (size_t)(row0 + r) * K);
            gp += kt * 32 + c16 * 8;
            uint32_t sa = sb + PARAMB + st * STAGE + half * BOFF + plane * PLANE +
                          r * 80 + c16 * 16;
            CP_ASYNC16(sa, gp);
        }
    };

    const int NC = K >> 5;
    issue(0, 0); CP_COMMIT();
    issue(1, 1); CP_COMMIT();

    float acc[4][4][4];
#pragma unroll
    for (int a = 0; a < 4; ++a)
#pragma unroll
        for (int b = 0; b < 4; ++b)
#pragma unroll
            for (int d = 0; d < 4; ++d) acc[a][b][d] = 0.f;

    // ldmatrix address components (bytes)
    uint32_t a_row[4], b_row[2];
#pragma unroll
    for (int mf = 0; mf < 4; ++mf)
        a_row[mf] = (uint32_t)(warp_m * 64 + mf * 16 + (lane & 15)) * 80;
#pragma unroll
    for (int nf2 = 0; nf2 < 2; ++nf2)
        b_row[nf2] =
            (uint32_t)(warp_n * 32 + nf2 * 16 + (lane & 7) + ((lane >> 4) & 1) * 8) * 80;
    const uint32_t a_koff = (uint32_t)(lane >> 4) * 16;       // 0 or 16 bytes
    const uint32_t b_koff = (uint32_t)((lane >> 3) & 1) * 16; // 0 or 16 bytes

    for (int kt = 0; kt < NC; ++kt) {
        CP_WAIT1();
        __syncthreads();
        const int nx = kt + 2;
        if (nx < NC) issue(nx, nx % 3);
        CP_COMMIT();

        const uint32_t base = sb + PARAMB + (uint32_t)(kt % 3) * STAGE;
#pragma unroll
        for (int k16 = 0; k16 < 2; ++k16) {
            const uint32_t kb = (uint32_t)k16 * 32;  // 16 elems * 2B
            uint32_t ah[4][4], al[4][4], bh[4][2], bl[4][2];
#pragma unroll
            for (int nf2 = 0; nf2 < 2; ++nf2) {
                uint32_t r0, r1, r2, r3;
                LDMX4(r0, r1, r2, r3, base + BOFF + b_row[nf2] + kb + b_koff);
                bh[nf2 * 2][0] = r0; bh[nf2 * 2][1] = r1;
                bh[nf2 * 2 + 1][0] = r2; bh[nf2 * 2 + 1][1] = r3;
                LDMX4(r0, r1, r2, r3, base + BOFF + PLANE + b_row[nf2] + kb + b_koff);
                bl[nf2 * 2][0] = r0; bl[nf2 * 2][1] = r1;
                bl[nf2 * 2 + 1][0] = r2; bl[nf2 * 2 + 1][1] = r3;
            }
#pragma unroll
            for (int mf = 0; mf < 4; ++mf)
                LDMX4(ah[mf][0], ah[mf][1], ah[mf][2], ah[mf][3],
                      base + a_row[mf] + kb + a_koff);
#pragma unroll
            for (int mf = 0; mf < 4; ++mf)
#pragma unroll
                for (int nf = 0; nf < 4; ++nf) {
                    MMA16816(acc[mf][nf], ah[mf], bh[nf][0], bh[nf][1]);
                    MMA16816(acc[mf][nf], ah[mf], bl[nf][0], bl[nf][1]);
                }
#pragma unroll
            for (int mf = 0; mf < 4; ++mf)
                LDMX4(al[mf][0], al[mf][1], al[mf][2], al[mf][3],
                      base + PLANE + a_row[mf] + kb + a_koff);
#pragma unroll
            for (int mf = 0; mf < 4; ++mf)
#pragma unroll
                for (int nf = 0; nf < 4; ++nf)
                    MMA16816(acc[mf][nf], al[mf], bh[nf][0], bh[nf][1]);
        }
    }

    // ---- epilogue ----
    // C frag: c0,c1 = D[row = lane/4][col = 2*(lane&3) + {0,1}], c2,c3 = row+8.
    // Column pair index p = col/2 -> generator g = p % 4 = lane & 3 (col0,
    // warp_n*16, nf*4 all = 0 mod 4). g in {2,3} -> identity.
    const int g = lane & 3;
    const float cA = (g < 2) ? 0.05f : 0.f;
    const float sgn = (g == 1) ? -1.f : 1.f;

#pragma unroll
    for (int nf = 0; nf < 4; ++nf) {
        const int cl = warp_n * 32 + nf * 8 + 2 * (lane & 3);
        const float b0 = smf[cl], b1 = smf[cl + 1];
        float rw0 = 0.f, rw1 = 0.f, cps0[8], cps1[8];
        if (KAN) {
            rw0 = smf[128 + cl];
            rw1 = smf[128 + cl + 1];
#pragma unroll
            for (int j = 0; j < 8; ++j) {
                cps0[j] = smf[256 + cl * 8 + j];
                cps1[j] = smf[256 + (cl + 1) * 8 + j];
            }
        }
#pragma unroll
        for (int mf = 0; mf < 4; ++mf) {
            const int m0 = row0 + warp_m * 64 + mf * 16 + (lane >> 2);
            float v0 = acc[mf][nf][0] + b0, v1 = acc[mf][nf][1] + b1;
            float v2 = acc[mf][nf][2] + b0, v3 = acc[mf][nf][3] + b1;
            if (KAN) {
                v0 = kan_eval(v0, cps0, rw0);
                v1 = kan_eval(v1, cps1, rw1);
                v2 = kan_eval(v2, cps0, rw0);
                v3 = kan_eval(v3, cps1, rw1);
                float t = v0;
                v0 = fmaf(cA, clip1f(sgn * v1), v0);
                v1 = fmaf(cA, clip1f(t), v1);
                t = v2;
                v2 = fmaf(cA, clip1f(sgn * v3), v2);
                v3 = fmaf(cA, clip1f(t), v3);
                __nv_bfloat16 h0 = __float2bfloat16_rn(v0), h1 = __float2bfloat16_rn(v1);
                __nv_bfloat16 h2 = __float2bfloat16_rn(v2), h3 = __float2bfloat16_rn(v3);
                const size_t i0 = (size_t)m0 * N + col0 + cl;
                const size_t i1 = (size_t)(m0 + 8) * N + col0 + cl;
                *(uint32_t*)(Chi + i0) =
                    ((uint32_t)__bfloat16_as_ushort(h1) << 16) | __bfloat16_as_ushort(h0);
                *(uint32_t*)(Chi + i1) =
                    ((uint32_t)__bfloat16_as_ushort(h3) << 16) | __bfloat16_as_ushort(h2);
                *(uint32_t*)(Clo + i0) =
                    pack_bf2(v0 - __bfloat162float(h0), v1 - __bfloat162float(h1));
                *(uint32_t*)(Clo + i1) =
                    pack_bf2(v2 - __bfloat162float(h2), v3 - __bfloat162float(h3));
            } else {
                const size_t i0 = (size_t)m0 * N + col0 + cl;
                const size_t i1 = (size_t)(m0 + 8) * N + col0 + cl;
                *(float2*)(Cf + i0) = make_float2(v0, v1);
                *(float2*)(Cf + i1) = make_float2(v2, v3);
            }
        }
    }
}

// ===========================================================================
// Launch
// ===========================================================================
static constexpr int SMEM_BYTES = 5120 + 3 * 40960;  // 128000

extern "C" void kernel_launch(void* const* d_in, const int* in_sizes, int n_in,
                              void* d_out, int out_size) {
    const float* x = (const float*)d_in[0];
    const float* W1 = (const float*)d_in[1];
    const float* b1 = (const float*)d_in[2];
    const float* cp1 = (const float*)d_in[3];
    const float* rw1 = (const float*)d_in[4];
    const float* W2 = (const float*)d_in[5];
    const float* b2 = (const float*)d_in[6];
    const float* cp2 = (const float*)d_in[7];
    const float* rw2 = (const float*)d_in[8];
    const float* W3 = (const float*)d_in[9];
    const float* b3 = (const float*)d_in[10];
    const float* cp3 = (const float*)d_in[11];
    const float* rw3 = (const float*)d_in[12];
    const float* Wo = (const float*)d_in[13];
    const float* bo = (const float*)d_in[14];

    static __nv_bfloat16 *Ah = nullptr, *Al, *Bh, *Bl, *Wh, *Wl;
    if (!Ah) {
        cudaGetSymbolAddress((void**)&Ah, g_Ahi);
        cudaGetSymbolAddress((void**)&Al, g_Alo);
        cudaGetSymbolAddress((void**)&Bh, g_Bhi);
        cudaGetSymbolAddress((void**)&Bl, g_Blo);
        cudaGetSymbolAddress((void**)&Wh, g_Whi);
        cudaGetSymbolAddress((void**)&Wl, g_Wlo);
        cudaFuncSetAttribute(gemm_mma<1>, cudaFuncAttributeMaxDynamicSharedMemorySize, SMEM_BYTES);
        cudaFuncSetAttribute(gemm_mma<0>, cudaFuncAttributeMaxDynamicSharedMemorySize, SMEM_BYTES);
    }

    // ---- weight split prepass (reads fp32 once, writes bf16 planes) ----
    wsplit<<<8388608 / 4 / 256, 256>>>((const float4*)W1, (uint2*)(Wh + W_OFF1),
                                       (uint2*)(Wl + W_OFF1), 8388608 / 4);
    wsplit<<<16777216 / 4 / 256, 256>>>((const float4*)W2, (uint2*)(Wh + W_OFF2),
                                        (uint2*)(Wl + W_OFF2), 16777216 / 4);
    wsplit<<<8388608 / 4 / 256, 256>>>((const float4*)W3, (uint2*)(Wh + W_OFF3),
                                       (uint2*)(Wl + W_OFF3), 8388608 / 4);
    wsplit<<<4194304 / 4 / 256, 256>>>((const float4*)Wo, (uint2*)(Wh + W_OFFO),
                                       (uint2*)(Wl + W_OFFO), 4194304 / 4);

    // ---- LN: x -> (Ah, Al) planes, K = 2048 ----
    ln_kernel<<<1024, 256>>>(x, Ah, Al);

    // ---- GEMM chain ----
    gemm_mma<1><<<dim3(32, 8), 256, SMEM_BYTES>>>(Ah, Al, Wh + W_OFF1, Wl + W_OFF1,
                                                  b1, cp1, rw1, nullptr, Bh, Bl,
                                                  4096, 2048);
    gemm_mma<1><<<dim3(32, 8), 256, SMEM_BYTES>>>(Bh, Bl, Wh + W_OFF2, Wl + W_OFF2,
                                                  b2, cp2, rw2, nullptr, Ah, Al,
                                                  4096, 4096);
    gemm_mma<1><<<dim3(16, 8), 256, SMEM_BYTES>>>(Ah, Al, Wh + W_OFF3, Wl + W_OFF3,
                                                  b3, cp3, rw3, nullptr, Bh, Bl,
                                                  2048, 4096);
    gemm_mma<0><<<dim3(16, 8), 256, SMEM_BYTES>>>(Bh, Bl, Wh + W_OFFO, Wl + W_OFFO,
                                                  bo, nullptr, nullptr, (float*)d_out,
                                                  nullptr, nullptr, 2048, 2048);
}